// round 7
// baseline (speedup 1.0000x reference)
#include <cuda_runtime.h>
#include <cstdint>

#define NB 8192
#define NM 50
#define ND 64

// =================== kernel 1 shared memory layout ==========================
constexpr int ME_ST = 68;             // me row stride (frag LDS conflict-free)
constexpr int OFF_ME0 = 0;            // 64 x 68  sample0 me (tf32, rows 50-63 zero)
constexpr int OFF_ME1 = 4352;         // 64 x 68  sample1
constexpr int OFF_W1F = 8704;         // ue_W1 in MMA B-fragment layout: 4096 words
                                      //   uint2 F[ks*8+nt][lane] = {W1[ks*8+q][nt*8+r4],
                                      //                             W1[ks*8+q+4][nt*8+r4]}
constexpr int OFF_B1S = 12800;        // 64   ue_b1
constexpr int OFF_ITS = 12864;        // 2 x 64 item emb
constexpr int OFF_CS  = 12992;        // 2 x 16 item-side att bias
constexpr int OFF_W2S = 13024;        // 2 x 16 at_W2
// Per-half scratch region R (256 floats each), time-phased aliasing.
constexpr int OFF_R   = 13056;        // 2 x 256
constexpr int OFF_MEM = 13568;        // 2 x 64 ints member ids
constexpr int SM1_FLOATS = 13696;
constexpr int SM1_BYTES  = SM1_FLOATS * 4;   // 54784 B -> 4 CTAs/SM

__device__ float g_dkl_partial[NB];
__device__ float g_hbar[NB * ND];
__device__ float g_gatt[NB * ND];

__device__ __forceinline__ float4 ld4(const float* p) { return __ldg((const float4*)p); }

__device__ __forceinline__ uint32_t f2tf32(float x) {
    uint32_t r;
    asm("cvt.rna.tf32.f32 %0, %1;" : "=r"(r) : "f"(x));
    return r;
}

__device__ __forceinline__ void mma_tf32(float& c0, float& c1, float& c2, float& c3,
                                         uint32_t a0, uint32_t a1, uint32_t a2, uint32_t a3,
                                         uint32_t b0, uint32_t b1)
{
    asm volatile(
        "mma.sync.aligned.m16n8k8.row.col.f32.tf32.tf32.f32 "
        "{%0,%1,%2,%3}, {%4,%5,%6,%7}, {%8,%9}, {%0,%1,%2,%3};"
        : "+f"(c0), "+f"(c1), "+f"(c2), "+f"(c3)
        : "r"(a0), "r"(a1), "r"(a2), "r"(a3), "r"(b0), "r"(b1));
}

#define HBAR(h) asm volatile("bar.sync %0, 128;" :: "r"(1 + (h)) : "memory")

// ============================ KERNEL 1 ======================================
// 2 samples per 256-thread CTA: warps 0-3 -> sample0, warps 4-7 -> sample1.
extern "C" __global__ void __launch_bounds__(256, 4)
agree_k1(
    const int*   __restrict__ group_inputs,
    const int*   __restrict__ item_inputs,
    const int*   __restrict__ group_members,
    const float* __restrict__ user_emb,
    const float* __restrict__ item_emb,
    const float* __restrict__ ue_W1, const float* __restrict__ ue_b1,
    const float* __restrict__ at_W1, const float* __restrict__ at_b1,
    const float* __restrict__ at_W2, const float* __restrict__ at_b2)
{
    extern __shared__ float sm[];
    uint32_t* smu = (uint32_t*)sm;
    const int tid  = threadIdx.x;
    const int bid  = blockIdx.x;
    const int lane = tid & 31;
    const int wrp  = tid >> 5;

    int* mem0 = (int*)(sm + OFF_MEM);
    int* mem1 = (int*)(sm + OFF_MEM + 64);

    // ---- stage: ids, vectors ----
    if (tid < NM) {
        mem0[tid] = group_members[group_inputs[bid * 2] * NM + tid];
    } else if (tid >= 64 && tid < 64 + NM) {
        mem1[tid - 64] = group_members[group_inputs[bid * 2 + 1] * NM + (tid - 64)];
    }
    if (tid < 64) {
        sm[OFF_ITS + tid] = __ldg(&item_emb[item_inputs[bid * 2] * ND + tid]);
    } else if (tid < 128) {
        sm[OFF_ITS + tid] = __ldg(&item_emb[item_inputs[bid * 2 + 1] * ND + (tid - 64)]);
    } else if (tid < 192) {
        sm[OFF_B1S + tid - 128] = __ldg(&ue_b1[tid - 128]);
    }
    // ---- stage ue_W1 into B-fragment layout (tf32) ----
    #pragma unroll
    for (int it = 0; it < 4; it++) {
        int idx = tid + it * 256;            // float4 index 0..1023
        int e0  = idx * 4;
        int k   = e0 >> 6, n = e0 & 63;      // 4 consecutive n, same k
        float4 v = ld4(&ue_W1[e0]);
        int ks = k >> 3, qq = k & 7;
        int q = qq & 3, slot = qq >> 2;
        int ntg = n >> 3, r4b = n & 7;       // r4b in {0,4}
        uint32_t* base = smu + OFF_W1F;
        int w0 = ((ks * 8 + ntg) * 32 + r4b * 4 + q) * 2 + slot;
        base[w0]      = f2tf32(v.x);
        base[w0 + 8]  = f2tf32(v.y);
        base[w0 + 16] = f2tf32(v.z);
        base[w0 + 24] = f2tf32(v.w);
    }
    __syncthreads();

    // ---- gather both me tiles (tf32), zero-pad rows 50..63 ----
    #pragma unroll
    for (int ii = 0; ii < 8; ii++) {
        int i   = tid + ii * 256;
        int row = i >> 4;
        int c4  = (i & 15) * 4;
        int hf  = row >> 6, lr = row & 63;
        int base = hf ? OFF_ME1 : OFF_ME0;
        uint4 u = make_uint4(0, 0, 0, 0);
        if (lr < NM) {
            int uid = hf ? mem1[lr] : mem0[lr];
            float4 v = ld4(&user_emb[uid * ND + c4]);
            u = make_uint4(f2tf32(v.x), f2tf32(v.y), f2tf32(v.z), f2tf32(v.w));
        }
        *(uint4*)&smu[base + row * ME_ST + c4] = u;
    }
    __syncthreads();

    // ======================= per-half (128 threads) =========================
    const int half = wrp >> 2;
    const int ht   = tid & 127;
    const int mt   = wrp & 3;
    const int r4   = lane >> 2;
    const int q    = lane & 3;
    const int sid  = bid * 2 + half;
    const int meb  = half ? OFF_ME1 : OFF_ME0;
    const int RB   = OFF_R + half * 256;

    const int row0 = mt * 16 + r4, row1 = row0 + 8;
    const bool v0r = (row0 < NM), v1r = (row1 < NM);
    const int abase = meb + row0 * ME_ST + q;
    const uint2* w1f = (const uint2*)(smu + OFF_W1F);

    // ---- P1: h1 = me @ W1. 4 independent acc chains, B via LDS.64 frags ----
    #pragma unroll
    for (int ntb = 0; ntb < 2; ntb++) {
        float c[4][4] = {};
        #pragma unroll
        for (int ks = 0; ks < 8; ks++) {
            uint32_t a0 = smu[abase + ks * 8];
            uint32_t a1 = smu[abase + ks * 8 + 8 * ME_ST];
            uint32_t a2 = smu[abase + ks * 8 + 4];
            uint32_t a3 = smu[abase + ks * 8 + 4 + 8 * ME_ST];
            uint2 b[4];
            #pragma unroll
            for (int nt = 0; nt < 4; nt++)
                b[nt] = w1f[(ks * 8 + ntb * 4 + nt) * 32 + lane];
            #pragma unroll
            for (int nt = 0; nt < 4; nt++)
                mma_tf32(c[nt][0], c[nt][1], c[nt][2], c[nt][3],
                         a0, a1, a2, a3, b[nt].x, b[nt].y);
        }
        #pragma unroll
        for (int nt = 0; nt < 4; nt++) {
            const int n0 = ntb * 32 + nt * 8;
            const int col0 = n0 + 2 * q, col1 = col0 + 1;
            float h00 = c[nt][0] + sm[OFF_B1S + col0], h01 = c[nt][1] + sm[OFF_B1S + col1];
            float h10 = c[nt][2] + sm[OFF_B1S + col0], h11 = c[nt][3] + sm[OFF_B1S + col1];
            float s0 = (v0r ? fmaxf(h00, 0.f) : 0.f) + (v1r ? fmaxf(h10, 0.f) : 0.f);
            float s1 = (v0r ? fmaxf(h01, 0.f) : 0.f) + (v1r ? fmaxf(h11, 0.f) : 0.f);
            #pragma unroll
            for (int o = 4; o < 32; o <<= 1) {
                s0 += __shfl_xor_sync(0xffffffff, s0, o);
                s1 += __shfl_xor_sync(0xffffffff, s1, o);
            }
            if (lane < 4) {
                sm[RB + mt * 64 + n0 + 2 * lane]     = s0;
                sm[RB + mt * 64 + n0 + 2 * lane + 1] = s1;
            }
        }
    }
    HBAR(half);

    // ---- hbar -> gmem ; c[j] ; at_W2 stage ---------------------------------
    if (ht < 64) {
        float s = sm[RB + ht] + sm[RB + 64 + ht] + sm[RB + 128 + ht] + sm[RB + 192 + ht];
        g_hbar[sid * ND + ht] = s * (1.0f / (float)NM);
    } else if (ht < 80) {
        int j = ht - 64;
        float s = __ldg(&at_b1[j]);
        #pragma unroll 8
        for (int k = 0; k < ND; k++)
            s += sm[OFF_ITS + half * 64 + k] * __ldg(&at_W1[(ND + k) * 16 + j]);
        sm[OFF_CS + half * 16 + j] = s;
    } else if (ht < 96) {
        sm[OFF_W2S + half * 16 + ht - 80] = __ldg(&at_W2[ht - 80]);
    }
    HBAR(half);

    // ---- P3+P4: attention MMA (B via LDG+cvt), fused relu·at_W2 -> logits --
    {
        float c[2][4] = {};
        #pragma unroll
        for (int ks = 0; ks < 8; ks++) {
            uint32_t a0 = smu[abase + ks * 8];
            uint32_t a1 = smu[abase + ks * 8 + 8 * ME_ST];
            uint32_t a2 = smu[abase + ks * 8 + 4];
            uint32_t a3 = smu[abase + ks * 8 + 4 + 8 * ME_ST];
            uint32_t b[2][2];
            #pragma unroll
            for (int nt = 0; nt < 2; nt++) {
                b[nt][0] = f2tf32(__ldg(&at_W1[(q + ks * 8) * 16 + nt * 8 + r4]));
                b[nt][1] = f2tf32(__ldg(&at_W1[(q + 4 + ks * 8) * 16 + nt * 8 + r4]));
            }
            #pragma unroll
            for (int nt = 0; nt < 2; nt++)
                mma_tf32(c[nt][0], c[nt][1], c[nt][2], c[nt][3],
                         a0, a1, a2, a3, b[nt][0], b[nt][1]);
        }
        float l0 = 0.f, l1 = 0.f;
        #pragma unroll
        for (int nt = 0; nt < 2; nt++) {
            const int col0 = nt * 8 + 2 * q, col1 = col0 + 1;
            float w20 = sm[OFF_W2S + half * 16 + col0];
            float w21 = sm[OFF_W2S + half * 16 + col1];
            float cc0 = sm[OFF_CS + half * 16 + col0];
            float cc1 = sm[OFF_CS + half * 16 + col1];
            l0 += fmaxf(c[nt][0] + cc0, 0.f) * w20 + fmaxf(c[nt][1] + cc1, 0.f) * w21;
            l1 += fmaxf(c[nt][2] + cc0, 0.f) * w20 + fmaxf(c[nt][3] + cc1, 0.f) * w21;
        }
        l0 += __shfl_xor_sync(0xffffffff, l0, 1);
        l0 += __shfl_xor_sync(0xffffffff, l0, 2);
        l1 += __shfl_xor_sync(0xffffffff, l1, 1);
        l1 += __shfl_xor_sync(0xffffffff, l1, 2);
        if (q == 0) {
            float b2 = __ldg(&at_b2[0]);
            sm[RB + mt * 16 + r4]     = l0 + b2;   // logits in R[0..63]
            sm[RB + mt * 16 + r4 + 8] = l1 + b2;
        }
    }
    HBAR(half);

    // ---- softmax over 50: single warp per half -----------------------------
    if ((wrp & 3) == 0) {
        const int m0 = lane, m1 = lane + 32;
        float l0v = sm[RB + m0];
        float l1v = (m1 < NM) ? sm[RB + m1] : -3.0e38f;
        float v = fmaxf(l0v, l1v);
        #pragma unroll
        for (int o = 16; o > 0; o >>= 1) v = fmaxf(v, __shfl_xor_sync(0xffffffff, v, o));
        float e0 = __expf(l0v - v);
        float e1 = (m1 < NM) ? __expf(l1v - v) : 0.f;
        float ss = e0 + e1;
        #pragma unroll
        for (int o = 16; o > 0; o >>= 1) ss += __shfl_xor_sync(0xffffffff, ss, o);
        float inv = 1.0f / ss;
        sm[RB + 192 + m0] = e0 * inv;              // wsm in R[192..255]
        if (m1 < NM) sm[RB + 192 + m1] = e1 * inv;
    }
    HBAR(half);

    // ---- pool: g_att = sum_m w[m] * me[m] ----------------------------------
    {
        const int j  = ht & 63;
        const int mq = ht >> 6;
        const int m0 = mq * 25, m1 = m0 + 25;
        float s = 0.f;
        #pragma unroll 5
        for (int m = m0; m < m1; m++)
            s += sm[RB + 192 + m] * sm[meb + m * ME_ST + j];
        sm[RB + 64 + mq * 64 + j] = s;             // pool partials R[64..191]
    }
    HBAR(half);
    if (ht < 64) {
        g_gatt[sid * ND + ht] = sm[RB + 64 + ht] + sm[RB + 128 + ht];
    }
}

// ============================ KERNEL 2 ======================================
// Warp-per-sample, register-resident activations, shuffle broadcast.
// No shared memory, no barriers. 8 samples per 256-thread CTA.
extern "C" __global__ void __launch_bounds__(256)
agree_k2(
    const int*   __restrict__ group_inputs,
    const int*   __restrict__ item_inputs,
    const float* __restrict__ item_emb,
    const float* __restrict__ group_emb,
    const float* __restrict__ ue_W2, const float* __restrict__ ue_b2,
    const float* __restrict__ ge_W1, const float* __restrict__ ge_b1,
    const float* __restrict__ ge_W2, const float* __restrict__ ge_b2,
    const float* __restrict__ pr_W1, const float* __restrict__ pr_b1,
    const float* __restrict__ pr_W2, const float* __restrict__ pr_b2,
    float* __restrict__ y_out)
{
    const int tid  = threadIdx.x;
    const int lane = tid & 31;
    const int wrp  = tid >> 5;
    const int sid  = blockIdx.x * 8 + wrp;
    const unsigned FULL = 0xffffffffu;

    const int gidx = __ldg(&group_inputs[sid]);
    const int iidx = __ldg(&item_inputs[sid]);

    // hbar resident: lane holds cols {lane, lane+32}
    float h0 = __ldg(&g_hbar[sid * ND + lane]);
    float h1 = __ldg(&g_hbar[sid * ND + 32 + lane]);

    // ---- A: uagg = relu(hbar @ ue_W2 + b2); lane holds cols {2l, 2l+1} ----
    float u0 = __ldg(&ue_b2[2 * lane]), u1 = __ldg(&ue_b2[2 * lane + 1]);
    #pragma unroll
    for (int k = 0; k < 64; k++) {
        float a = __shfl_sync(FULL, (k < 32) ? h0 : h1, k & 31);
        float2 w = __ldg((const float2*)&ue_W2[k * 64 + 2 * lane]);
        u0 += a * w.x; u1 += a * w.y;
    }
    u0 = fmaxf(u0, 0.f); u1 = fmaxf(u1, 0.f);

    // ---- B: z = relu(uagg @ ge_W1 + b1); lane holds cols {l, l+32, l+64} ---
    float z0 = __ldg(&ge_b1[lane]);
    float z1 = __ldg(&ge_b1[lane + 32]);
    float z2 = __ldg(&ge_b1[lane + 64]);
    #pragma unroll
    for (int k = 0; k < 64; k++) {
        float a = __shfl_sync(FULL, (k & 1) ? u1 : u0, k >> 1);
        z0 += a * __ldg(&ge_W1[k * 96 + lane]);
        z1 += a * __ldg(&ge_W1[k * 96 + 32 + lane]);
        z2 += a * __ldg(&ge_W1[k * 96 + 64 + lane]);
    }
    z0 = fmaxf(z0, 0.f); z1 = fmaxf(z1, 0.f); z2 = fmaxf(z2, 0.f);

    // ---- C: z_mu (first 64 cols of ge_W2) -> dkl ---------------------------
    float m0 = __ldg(&ge_b2[2 * lane]), m1 = __ldg(&ge_b2[2 * lane + 1]);
    #pragma unroll
    for (int k = 0; k < 96; k++) {
        float a = __shfl_sync(FULL, (k < 32) ? z0 : ((k < 64) ? z1 : z2), k & 31);
        float2 w = __ldg((const float2*)&ge_W2[k * 128 + 2 * lane]);
        m0 += a * w.x; m1 += a * w.y;
    }
    float2 gev = __ldg((const float2*)&group_emb[gidx * ND + 2 * lane]);
    {
        float d0 = gev.x - m0, d1 = gev.y - m1;
        float p = d0 * d0 + d1 * d1;
        #pragma unroll
        for (int o = 16; o > 0; o >>= 1) p += __shfl_xor_sync(FULL, p, o);
        if (lane == 0) g_dkl_partial[sid] = p;
    }

    // ---- D: prediction head ------------------------------------------------
    float2 itv = __ldg((const float2*)&item_emb[iidx * ND + 2 * lane]);
    float2 gav = __ldg((const float2*)&g_gatt[sid * ND + 2 * lane]);
    float g0 = gav.x + gev.x, g1 = gav.y + gev.y;
    float hj[8] = {};
    #pragma unroll
    for (int c = 0; c < 2; c++) {
        int col = 2 * lane + c;
        float gg = c ? g1 : g0;
        float iv = c ? itv.y : itv.x;
        float v = gg * iv;
        float4 wa0 = ld4(&pr_W1[col * 8]),         wa1 = ld4(&pr_W1[col * 8 + 4]);
        float4 wb0 = ld4(&pr_W1[(64 + col) * 8]),  wb1 = ld4(&pr_W1[(64 + col) * 8 + 4]);
        float4 wc0 = ld4(&pr_W1[(128 + col) * 8]), wc1 = ld4(&pr_W1[(128 + col) * 8 + 4]);
        hj[0] += v * wa0.x + gg * wb0.x + iv * wc0.x;
        hj[1] += v * wa0.y + gg * wb0.y + iv * wc0.y;
        hj[2] += v * wa0.z + gg * wb0.z + iv * wc0.z;
        hj[3] += v * wa0.w + gg * wb0.w + iv * wc0.w;
        hj[4] += v * wa1.x + gg * wb1.x + iv * wc1.x;
        hj[5] += v * wa1.y + gg * wb1.y + iv * wc1.y;
        hj[6] += v * wa1.z + gg * wb1.z + iv * wc1.z;
        hj[7] += v * wa1.w + gg * wb1.w + iv * wc1.w;
    }
    #pragma unroll
    for (int j = 0; j < 8; j++) {
        #pragma unroll
        for (int o = 16; o > 0; o >>= 1) hj[j] += __shfl_xor_sync(FULL, hj[j], o);
    }
    if (lane == 0) {
        float s = __ldg(&pr_b2[0]);
        #pragma unroll
        for (int j = 0; j < 8; j++)
            s += fmaxf(hj[j] + __ldg(&pr_b1[j]), 0.f) * __ldg(&pr_W2[j]);
        y_out[sid] = 1.0f / (1.0f + __expf(-s));
    }
}

// Deterministic final reduction for dkl.
extern "C" __global__ void __launch_bounds__(1024)
reduce_dkl_kernel(float* __restrict__ out, int out_idx)
{
    __shared__ float red[1024];
    float s = 0.f;
    #pragma unroll
    for (int i = 0; i < NB / 1024; i++) s += g_dkl_partial[threadIdx.x + i * 1024];
    red[threadIdx.x] = s;
    __syncthreads();
    for (int st = 512; st > 0; st >>= 1) {
        if (threadIdx.x < st) red[threadIdx.x] += red[threadIdx.x + st];
        __syncthreads();
    }
    if (threadIdx.x == 0) out[out_idx] = red[0] * (1.0f / (float)NB);
}

extern "C" void kernel_launch(void* const* d_in, const int* in_sizes, int n_in,
                              void* d_out, int out_size)
{
    cudaFuncSetAttribute(agree_k1, cudaFuncAttributeMaxDynamicSharedMemorySize, SM1_BYTES);

    agree_k1<<<NB / 2, 256, SM1_BYTES>>>(
        (const int*)d_in[0],
        (const int*)d_in[1],
        (const int*)d_in[2],
        (const float*)d_in[3],
        (const float*)d_in[4],
        (const float*)d_in[6],  (const float*)d_in[7],
        (const float*)d_in[14], (const float*)d_in[15],
        (const float*)d_in[16], (const float*)d_in[17]);

    agree_k2<<<NB / 8, 256>>>(
        (const int*)d_in[0],
        (const int*)d_in[1],
        (const float*)d_in[4],
        (const float*)d_in[5],
        (const float*)d_in[8],  (const float*)d_in[9],
        (const float*)d_in[10], (const float*)d_in[11],
        (const float*)d_in[12], (const float*)d_in[13],
        (const float*)d_in[18], (const float*)d_in[19],
        (const float*)d_in[20], (const float*)d_in[21],
        (float*)d_out);

    reduce_dkl_kernel<<<1, 1024>>>((float*)d_out, out_size - 1);
}

// round 9
// speedup vs baseline: 1.2816x; 1.2816x over previous
#include <cuda_runtime.h>
#include <cstdint>

#define NB 8192
#define NM 50
#define ND 64

// =================== kernel 1 shared memory layout ==========================
constexpr int ME_ST = 68;             // me row stride (frag LDS conflict-free)
constexpr int OFF_ME0 = 0;            // 64 x 68  sample0 me (tf32, rows 50-63 zero)
constexpr int OFF_ME1 = 4352;         // 64 x 68  sample1  (= OFF_ME0 + 64*ME_ST)
constexpr int OFF_B1S = 8704;         // 64   ue_b1
constexpr int OFF_ITS = 8768;         // 2 x 64 item emb
constexpr int OFF_CS  = 8896;         // 2 x 16 item-side att bias
constexpr int OFF_W2S = 8928;         // 2 x 16 at_W2
constexpr int OFF_R   = 8960;         // 2 x 256 per-half scratch (time-phased)
constexpr int OFF_MEM = 9472;         // 2 x 64 ints member ids
constexpr int SM1_FLOATS = 9600;
constexpr int SM1_BYTES  = SM1_FLOATS * 4;   // 38400 B -> 5 CTAs/SM

__device__ float g_dkl_partial[NB];
__device__ float g_hbar[NB * ND];
__device__ float g_gatt[NB * ND];
// Precomputed tf32 B-fragments (written once per launch by prep_weights):
//   g_w1f[(ks*8+nt)*32 + lane] = { W1[ks*8+q][nt*8+r4], W1[ks*8+4+q][nt*8+r4] }
//   g_atf[(ks*2+nt)*32 + lane] = { atW1[ks*8+q][nt*8+r4], atW1[ks*8+4+q][nt*8+r4] }
__device__ uint2 g_w1f[2048];
__device__ uint2 g_atf[512];

__device__ __forceinline__ float4 ld4(const float* p) { return __ldg((const float4*)p); }

__device__ __forceinline__ uint32_t f2tf32(float x) {
    uint32_t r;
    asm("cvt.rna.tf32.f32 %0, %1;" : "=r"(r) : "f"(x));
    return r;
}

__device__ __forceinline__ void mma_tf32(float& c0, float& c1, float& c2, float& c3,
                                         uint32_t a0, uint32_t a1, uint32_t a2, uint32_t a3,
                                         uint32_t b0, uint32_t b1)
{
    asm volatile(
        "mma.sync.aligned.m16n8k8.row.col.f32.tf32.tf32.f32 "
        "{%0,%1,%2,%3}, {%4,%5,%6,%7}, {%8,%9}, {%0,%1,%2,%3};"
        : "+f"(c0), "+f"(c1), "+f"(c2), "+f"(c3)
        : "r"(a0), "r"(a1), "r"(a2), "r"(a3), "r"(b0), "r"(b1));
}

#define HBAR(h) asm volatile("bar.sync %0, 128;" :: "r"(1 + (h)) : "memory")

// ============================ PREP KERNEL ===================================
// One-time conversion of ue_W1 / at_W1 into tf32 MMA B-fragment layout.
extern "C" __global__ void __launch_bounds__(256)
prep_weights(const float* __restrict__ ue_W1, const float* __restrict__ at_W1)
{
    int idx = blockIdx.x * 256 + threadIdx.x;
    if (idx < 2048) {
        int pair = idx >> 5, lane = idx & 31;
        int ks = pair >> 3, nt = pair & 7;
        int q = lane & 3, r4 = lane >> 2;
        uint2 u;
        u.x = f2tf32(__ldg(&ue_W1[(ks * 8 + q) * 64 + nt * 8 + r4]));
        u.y = f2tf32(__ldg(&ue_W1[(ks * 8 + 4 + q) * 64 + nt * 8 + r4]));
        g_w1f[idx] = u;
    }
    int jdx = idx - 2048;
    if (jdx >= 0 && jdx < 512) {
        int pair = jdx >> 5, lane = jdx & 31;
        int ks = pair >> 1, nt = pair & 1;
        int q = lane & 3, r4 = lane >> 2;
        uint2 u;
        u.x = f2tf32(__ldg(&at_W1[(ks * 8 + q) * 16 + nt * 8 + r4]));
        u.y = f2tf32(__ldg(&at_W1[(ks * 8 + 4 + q) * 16 + nt * 8 + r4]));
        g_atf[jdx] = u;
    }
}

// ============================ KERNEL 1 ======================================
// 2 samples per 256-thread CTA: warps 0-3 -> sample0, warps 4-7 -> sample1.
extern "C" __global__ void __launch_bounds__(256, 5)
agree_k1(
    const int*   __restrict__ group_inputs,
    const int*   __restrict__ item_inputs,
    const int*   __restrict__ group_members,
    const float* __restrict__ user_emb,
    const float* __restrict__ item_emb,
    const float* __restrict__ ue_b1,
    const float* __restrict__ at_W1, const float* __restrict__ at_b1,
    const float* __restrict__ at_W2, const float* __restrict__ at_b2)
{
    extern __shared__ float sm[];
    uint32_t* smu = (uint32_t*)sm;
    const int tid  = threadIdx.x;
    const int bid  = blockIdx.x;
    const int lane = tid & 31;
    const int wrp  = tid >> 5;

    int* mem0 = (int*)(sm + OFF_MEM);
    int* mem1 = (int*)(sm + OFF_MEM + 64);

    // ---- stage: ids, vectors ----
    if (tid < NM) {
        mem0[tid] = group_members[group_inputs[bid * 2] * NM + tid];
    } else if (tid >= 64 && tid < 64 + NM) {
        mem1[tid - 64] = group_members[group_inputs[bid * 2 + 1] * NM + (tid - 64)];
    }
    if (tid < 64) {
        sm[OFF_ITS + tid] = __ldg(&item_emb[item_inputs[bid * 2] * ND + tid]);
    } else if (tid < 128) {
        sm[OFF_ITS + tid] = __ldg(&item_emb[item_inputs[bid * 2 + 1] * ND + (tid - 64)]);
    } else if (tid < 192) {
        sm[OFF_B1S + tid - 128] = __ldg(&ue_b1[tid - 128]);
    }
    __syncthreads();

    // ---- gather both me tiles (tf32), zero-pad rows 50..63 ----
    // Sample-local row index lr addresses within each tile; hf selects the tile
    // base. (lr, not row: row carries the +64 tile offset already.)
    #pragma unroll
    for (int ii = 0; ii < 8; ii++) {
        int i   = tid + ii * 256;
        int row = i >> 4;
        int c4  = (i & 15) * 4;
        int hf  = row >> 6, lr = row & 63;
        int base = hf ? OFF_ME1 : OFF_ME0;
        uint4 u = make_uint4(0, 0, 0, 0);
        if (lr < NM) {
            int uid = hf ? mem1[lr] : mem0[lr];
            float4 v = ld4(&user_emb[uid * ND + c4]);
            u = make_uint4(f2tf32(v.x), f2tf32(v.y), f2tf32(v.z), f2tf32(v.w));
        }
        *(uint4*)&smu[base + lr * ME_ST + c4] = u;
    }
    __syncthreads();

    // ======================= per-half (128 threads) =========================
    const int half = wrp >> 2;
    const int ht   = tid & 127;
    const int mt   = wrp & 3;
    const int r4   = lane >> 2;
    const int q    = lane & 3;
    const int sid  = bid * 2 + half;
    const int meb  = half ? OFF_ME1 : OFF_ME0;
    const int RB   = OFF_R + half * 256;

    const int row0 = mt * 16 + r4, row1 = row0 + 8;
    const bool v0r = (row0 < NM), v1r = (row1 < NM);
    const int abase = meb + row0 * ME_ST + q;

    // ---- P1: h1 = me @ W1. B-frags via LDG.64 from precomputed g_w1f ------
    #pragma unroll
    for (int ntb = 0; ntb < 2; ntb++) {
        float c[4][4] = {};
        #pragma unroll
        for (int ks = 0; ks < 8; ks++) {
            uint32_t a0 = smu[abase + ks * 8];
            uint32_t a1 = smu[abase + ks * 8 + 8 * ME_ST];
            uint32_t a2 = smu[abase + ks * 8 + 4];
            uint32_t a3 = smu[abase + ks * 8 + 4 + 8 * ME_ST];
            uint2 b[4];
            #pragma unroll
            for (int nt = 0; nt < 4; nt++)
                b[nt] = __ldg(&g_w1f[(ks * 8 + ntb * 4 + nt) * 32 + lane]);
            #pragma unroll
            for (int nt = 0; nt < 4; nt++)
                mma_tf32(c[nt][0], c[nt][1], c[nt][2], c[nt][3],
                         a0, a1, a2, a3, b[nt].x, b[nt].y);
        }
        #pragma unroll
        for (int nt = 0; nt < 4; nt++) {
            const int n0 = ntb * 32 + nt * 8;
            const int col0 = n0 + 2 * q, col1 = col0 + 1;
            float h00 = c[nt][0] + sm[OFF_B1S + col0], h01 = c[nt][1] + sm[OFF_B1S + col1];
            float h10 = c[nt][2] + sm[OFF_B1S + col0], h11 = c[nt][3] + sm[OFF_B1S + col1];
            float s0 = (v0r ? fmaxf(h00, 0.f) : 0.f) + (v1r ? fmaxf(h10, 0.f) : 0.f);
            float s1 = (v0r ? fmaxf(h01, 0.f) : 0.f) + (v1r ? fmaxf(h11, 0.f) : 0.f);
            #pragma unroll
            for (int o = 4; o < 32; o <<= 1) {
                s0 += __shfl_xor_sync(0xffffffff, s0, o);
                s1 += __shfl_xor_sync(0xffffffff, s1, o);
            }
            if (lane < 4) {
                sm[RB + mt * 64 + n0 + 2 * lane]     = s0;
                sm[RB + mt * 64 + n0 + 2 * lane + 1] = s1;
            }
        }
    }
    HBAR(half);

    // ---- hbar -> gmem ; c[j] ; at_W2 stage ---------------------------------
    if (ht < 64) {
        float s = sm[RB + ht] + sm[RB + 64 + ht] + sm[RB + 128 + ht] + sm[RB + 192 + ht];
        g_hbar[sid * ND + ht] = s * (1.0f / (float)NM);
    } else if (ht < 80) {
        int j = ht - 64;
        float s = __ldg(&at_b1[j]);
        #pragma unroll 8
        for (int k = 0; k < ND; k++)
            s += sm[OFF_ITS + half * 64 + k] * __ldg(&at_W1[(ND + k) * 16 + j]);
        sm[OFF_CS + half * 16 + j] = s;
    } else if (ht < 96) {
        sm[OFF_W2S + half * 16 + ht - 80] = __ldg(&at_W2[ht - 80]);
    }
    HBAR(half);

    // ---- P3+P4: attention MMA (B via LDG.64 g_atf), fused epilogue ---------
    {
        float c[2][4] = {};
        #pragma unroll
        for (int ks = 0; ks < 8; ks++) {
            uint32_t a0 = smu[abase + ks * 8];
            uint32_t a1 = smu[abase + ks * 8 + 8 * ME_ST];
            uint32_t a2 = smu[abase + ks * 8 + 4];
            uint32_t a3 = smu[abase + ks * 8 + 4 + 8 * ME_ST];
            uint2 b[2];
            #pragma unroll
            for (int nt = 0; nt < 2; nt++)
                b[nt] = __ldg(&g_atf[(ks * 2 + nt) * 32 + lane]);
            #pragma unroll
            for (int nt = 0; nt < 2; nt++)
                mma_tf32(c[nt][0], c[nt][1], c[nt][2], c[nt][3],
                         a0, a1, a2, a3, b[nt].x, b[nt].y);
        }
        float l0 = 0.f, l1 = 0.f;
        #pragma unroll
        for (int nt = 0; nt < 2; nt++) {
            const int col0 = nt * 8 + 2 * q, col1 = col0 + 1;
            float w20 = sm[OFF_W2S + half * 16 + col0];
            float w21 = sm[OFF_W2S + half * 16 + col1];
            float cc0 = sm[OFF_CS + half * 16 + col0];
            float cc1 = sm[OFF_CS + half * 16 + col1];
            l0 += fmaxf(c[nt][0] + cc0, 0.f) * w20 + fmaxf(c[nt][1] + cc1, 0.f) * w21;
            l1 += fmaxf(c[nt][2] + cc0, 0.f) * w20 + fmaxf(c[nt][3] + cc1, 0.f) * w21;
        }
        l0 += __shfl_xor_sync(0xffffffff, l0, 1);
        l0 += __shfl_xor_sync(0xffffffff, l0, 2);
        l1 += __shfl_xor_sync(0xffffffff, l1, 1);
        l1 += __shfl_xor_sync(0xffffffff, l1, 2);
        if (q == 0) {
            float b2 = __ldg(&at_b2[0]);
            sm[RB + mt * 16 + r4]     = l0 + b2;   // logits in R[0..63]
            sm[RB + mt * 16 + r4 + 8] = l1 + b2;
        }
    }
    HBAR(half);

    // ---- softmax over 50: single warp per half -----------------------------
    if ((wrp & 3) == 0) {
        const int m0 = lane, m1 = lane + 32;
        float l0v = sm[RB + m0];
        float l1v = (m1 < NM) ? sm[RB + m1] : -3.0e38f;
        float v = fmaxf(l0v, l1v);
        #pragma unroll
        for (int o = 16; o > 0; o >>= 1) v = fmaxf(v, __shfl_xor_sync(0xffffffff, v, o));
        float e0 = __expf(l0v - v);
        float e1 = (m1 < NM) ? __expf(l1v - v) : 0.f;
        float ss = e0 + e1;
        #pragma unroll
        for (int o = 16; o > 0; o >>= 1) ss += __shfl_xor_sync(0xffffffff, ss, o);
        float inv = 1.0f / ss;
        sm[RB + 192 + m0] = e0 * inv;              // wsm in R[192..255]
        if (m1 < NM) sm[RB + 192 + m1] = e1 * inv;
    }
    HBAR(half);

    // ---- pool: g_att = sum_m w[m] * me[m] ----------------------------------
    {
        const int j  = ht & 63;
        const int mq = ht >> 6;
        const int m0 = mq * 25, m1 = m0 + 25;
        float s = 0.f;
        #pragma unroll 5
        for (int m = m0; m < m1; m++)
            s += sm[RB + 192 + m] * sm[meb + m * ME_ST + j];
        sm[RB + 64 + mq * 64 + j] = s;             // pool partials R[64..191]
    }
    HBAR(half);
    if (ht < 64) {
        g_gatt[sid * ND + ht] = sm[RB + 64 + ht] + sm[RB + 128 + ht];
    }
}

// ============================ KERNEL 2 ======================================
// Warp-per-sample, register-resident activations, shuffle broadcast.
extern "C" __global__ void __launch_bounds__(256)
agree_k2(
    const int*   __restrict__ group_inputs,
    const int*   __restrict__ item_inputs,
    const float* __restrict__ item_emb,
    const float* __restrict__ group_emb,
    const float* __restrict__ ue_W2, const float* __restrict__ ue_b2,
    const float* __restrict__ ge_W1, const float* __restrict__ ge_b1,
    const float* __restrict__ ge_W2, const float* __restrict__ ge_b2,
    const float* __restrict__ pr_W1, const float* __restrict__ pr_b1,
    const float* __restrict__ pr_W2, const float* __restrict__ pr_b2,
    float* __restrict__ y_out)
{
    const int tid  = threadIdx.x;
    const int lane = tid & 31;
    const int wrp  = tid >> 5;
    const int sid  = blockIdx.x * 8 + wrp;
    const unsigned FULL = 0xffffffffu;

    const int gidx = __ldg(&group_inputs[sid]);
    const int iidx = __ldg(&item_inputs[sid]);

    float h0 = __ldg(&g_hbar[sid * ND + lane]);
    float h1 = __ldg(&g_hbar[sid * ND + 32 + lane]);

    // ---- A: uagg = relu(hbar @ ue_W2 + b2) ----
    float u0 = __ldg(&ue_b2[2 * lane]), u1 = __ldg(&ue_b2[2 * lane + 1]);
    #pragma unroll
    for (int k = 0; k < 64; k++) {
        float a = __shfl_sync(FULL, (k < 32) ? h0 : h1, k & 31);
        float2 w = __ldg((const float2*)&ue_W2[k * 64 + 2 * lane]);
        u0 += a * w.x; u1 += a * w.y;
    }
    u0 = fmaxf(u0, 0.f); u1 = fmaxf(u1, 0.f);

    // ---- B: z = relu(uagg @ ge_W1 + b1) ----
    float z0 = __ldg(&ge_b1[lane]);
    float z1 = __ldg(&ge_b1[lane + 32]);
    float z2 = __ldg(&ge_b1[lane + 64]);
    #pragma unroll
    for (int k = 0; k < 64; k++) {
        float a = __shfl_sync(FULL, (k & 1) ? u1 : u0, k >> 1);
        z0 += a * __ldg(&ge_W1[k * 96 + lane]);
        z1 += a * __ldg(&ge_W1[k * 96 + 32 + lane]);
        z2 += a * __ldg(&ge_W1[k * 96 + 64 + lane]);
    }
    z0 = fmaxf(z0, 0.f); z1 = fmaxf(z1, 0.f); z2 = fmaxf(z2, 0.f);

    // ---- C: z_mu -> dkl ----
    float m0 = __ldg(&ge_b2[2 * lane]), m1 = __ldg(&ge_b2[2 * lane + 1]);
    #pragma unroll
    for (int k = 0; k < 96; k++) {
        float a = __shfl_sync(FULL, (k < 32) ? z0 : ((k < 64) ? z1 : z2), k & 31);
        float2 w = __ldg((const float2*)&ge_W2[k * 128 + 2 * lane]);
        m0 += a * w.x; m1 += a * w.y;
    }
    float2 gev = __ldg((const float2*)&group_emb[gidx * ND + 2 * lane]);
    {
        float d0 = gev.x - m0, d1 = gev.y - m1;
        float p = d0 * d0 + d1 * d1;
        #pragma unroll
        for (int o = 16; o > 0; o >>= 1) p += __shfl_xor_sync(FULL, p, o);
        if (lane == 0) g_dkl_partial[sid] = p;
    }

    // ---- D: prediction head ----
    float2 itv = __ldg((const float2*)&item_emb[iidx * ND + 2 * lane]);
    float2 gav = __ldg((const float2*)&g_gatt[sid * ND + 2 * lane]);
    float g0 = gav.x + gev.x, g1 = gav.y + gev.y;
    float hj[8] = {};
    #pragma unroll
    for (int c = 0; c < 2; c++) {
        int col = 2 * lane + c;
        float gg = c ? g1 : g0;
        float iv = c ? itv.y : itv.x;
        float v = gg * iv;
        float4 wa0 = ld4(&pr_W1[col * 8]),         wa1 = ld4(&pr_W1[col * 8 + 4]);
        float4 wb0 = ld4(&pr_W1[(64 + col) * 8]),  wb1 = ld4(&pr_W1[(64 + col) * 8 + 4]);
        float4 wc0 = ld4(&pr_W1[(128 + col) * 8]), wc1 = ld4(&pr_W1[(128 + col) * 8 + 4]);
        hj[0] += v * wa0.x + gg * wb0.x + iv * wc0.x;
        hj[1] += v * wa0.y + gg * wb0.y + iv * wc0.y;
        hj[2] += v * wa0.z + gg * wb0.z + iv * wc0.z;
        hj[3] += v * wa0.w + gg * wb0.w + iv * wc0.w;
        hj[4] += v * wa1.x + gg * wb1.x + iv * wc1.x;
        hj[5] += v * wa1.y + gg * wb1.y + iv * wc1.y;
        hj[6] += v * wa1.z + gg * wb1.z + iv * wc1.z;
        hj[7] += v * wa1.w + gg * wb1.w + iv * wc1.w;
    }
    #pragma unroll
    for (int j = 0; j < 8; j++) {
        #pragma unroll
        for (int o = 16; o > 0; o >>= 1) hj[j] += __shfl_xor_sync(FULL, hj[j], o);
    }
    if (lane == 0) {
        float s = __ldg(&pr_b2[0]);
        #pragma unroll
        for (int j = 0; j < 8; j++)
            s += fmaxf(hj[j] + __ldg(&pr_b1[j]), 0.f) * __ldg(&pr_W2[j]);
        y_out[sid] = 1.0f / (1.0f + __expf(-s));
    }
}

// Deterministic final reduction for dkl.
extern "C" __global__ void __launch_bounds__(1024)
reduce_dkl_kernel(float* __restrict__ out, int out_idx)
{
    __shared__ float red[1024];
    float s = 0.f;
    #pragma unroll
    for (int i = 0; i < NB / 1024; i++) s += g_dkl_partial[threadIdx.x + i * 1024];
    red[threadIdx.x] = s;
    __syncthreads();
    for (int st = 512; st > 0; st >>= 1) {
        if (threadIdx.x < st) red[threadIdx.x] += red[threadIdx.x + st];
        __syncthreads();
    }
    if (threadIdx.x == 0) out[out_idx] = red[0] * (1.0f / (float)NB);
}

extern "C" void kernel_launch(void* const* d_in, const int* in_sizes, int n_in,
                              void* d_out, int out_size)
{
    cudaFuncSetAttribute(agree_k1, cudaFuncAttributeMaxDynamicSharedMemorySize, SM1_BYTES);

    prep_weights<<<10, 256>>>((const float*)d_in[6], (const float*)d_in[14]);

    agree_k1<<<NB / 2, 256, SM1_BYTES>>>(
        (const int*)d_in[0],
        (const int*)d_in[1],
        (const int*)d_in[2],
        (const float*)d_in[3],
        (const float*)d_in[4],
        (const float*)d_in[7],
        (const float*)d_in[14], (const float*)d_in[15],
        (const float*)d_in[16], (const float*)d_in[17]);

    agree_k2<<<NB / 8, 256>>>(
        (const int*)d_in[0],
        (const int*)d_in[1],
        (const float*)d_in[4],
        (const float*)d_in[5],
        (const float*)d_in[8],  (const float*)d_in[9],
        (const float*)d_in[10], (const float*)d_in[11],
        (const float*)d_in[12], (const float*)d_in[13],
        (const float*)d_in[18], (const float*)d_in[19],
        (const float*)d_in[20], (const float*)d_in[21],
        (float*)d_out);

    reduce_dkl_kernel<<<1, 1024>>>((float*)d_out, out_size - 1);
}